// round 1
// baseline (speedup 1.0000x reference)
#include <cuda_runtime.h>
#include <cstdint>
#include <cstddef>

#define BATCH 8
#define CDIM  256
#define NPIX  4096
#define O1    1536
#define HIDD  512
#define NHEAD 8
#define DHEAD 64

// ---------------- scratch (device globals; no allocation allowed) ----------
__device__ float g_q[BATCH * HIDD * NPIX];     // 64 MB, elu1(q)  [b, h*64+d, n]
__device__ float g_k[BATCH * HIDD * NPIX];     // 64 MB, elu1(k)*(1+cs*cm)
__device__ float g_v[BATCH * HIDD * NPIX];     // 64 MB
__device__ float g_out2[BATCH * HIDD * NPIX];  // 64 MB, attention output [b, hid, n]
__device__ float g_kv[BATCH * NHEAD * DHEAD * DHEAD];
__device__ float g_ksum[BATCH * NHEAD * DHEAD];

// ---------------- f32x2 packed helpers (Blackwell FFMA2 path) --------------
__device__ __forceinline__ unsigned long long pack2(float lo, float hi) {
    unsigned long long r;
    asm("mov.b64 %0, {%1, %2};" : "=l"(r) : "f"(lo), "f"(hi));
    return r;
}
__device__ __forceinline__ void unpack2(unsigned long long v, float& lo, float& hi) {
    asm("mov.b64 {%0, %1}, %2;" : "=f"(lo), "=f"(hi) : "l"(v));
}
__device__ __forceinline__ unsigned long long ffma2(unsigned long long a,
                                                    unsigned long long b,
                                                    unsigned long long c) {
    unsigned long long d;
    asm("fma.rn.f32x2 %0, %1, %2, %3;" : "=l"(d) : "l"(a), "l"(b), "l"(c));
    return d;
}

__device__ __forceinline__ float elu1f(float x) {
    return x > 0.0f ? x + 1.0f : expf(x);
}

// ============================================================================
// Kernel 1: qkv = Wqkv[1536,256] @ x[b][256,4096], fused elu1 + contact scale.
// Block tile 128(o) x 128(n), K-step 8, 256 threads, 8x8 per-thread via f32x2.
// ============================================================================
__global__ __launch_bounds__(256) void qkv_gemm_kernel(
    const float* __restrict__ x, const float* __restrict__ Wqkv,
    const float* __restrict__ cm, const float* __restrict__ csp)
{
    __shared__ float As[8][132];   // [k][o], padded vs bank conflicts
    __shared__ float Bs[8][128];   // [k][n]

    const int b  = blockIdx.z;
    const int o0 = blockIdx.y * 128;
    const int n0 = blockIdx.x * 128;
    const int tid = threadIdx.x;
    const int tx = tid & 15;       // n-group
    const int ty = tid >> 4;       // o-group

    const float* xb = x + (size_t)b * CDIM * NPIX;

    unsigned long long acc[8][4];
#pragma unroll
    for (int i = 0; i < 8; i++)
#pragma unroll
        for (int j = 0; j < 4; j++) acc[i][j] = 0ULL;  // 0x0 == packed {0,0}

    const int arow = tid >> 1, ahalf = tid & 1;     // A: 128 rows x 8 k
    const int brow = tid >> 5, bcol = (tid & 31) * 4; // B: 8 k x 128 n

    // prefetch first tile
    float4 av = *reinterpret_cast<const float4*>(
        &Wqkv[(size_t)(o0 + arow) * CDIM + 0 + ahalf * 4]);
    float4 bv = *reinterpret_cast<const float4*>(
        &xb[(size_t)(0 + brow) * NPIX + n0 + bcol]);

    for (int k0 = 0; k0 < CDIM; k0 += 8) {
        __syncthreads();
        As[ahalf * 4 + 0][arow] = av.x;
        As[ahalf * 4 + 1][arow] = av.y;
        As[ahalf * 4 + 2][arow] = av.z;
        As[ahalf * 4 + 3][arow] = av.w;
        *reinterpret_cast<float4*>(&Bs[brow][bcol]) = bv;
        __syncthreads();

        if (k0 + 8 < CDIM) {  // prefetch next tile (hide DRAM latency behind FMAs)
            av = *reinterpret_cast<const float4*>(
                &Wqkv[(size_t)(o0 + arow) * CDIM + (k0 + 8) + ahalf * 4]);
            bv = *reinterpret_cast<const float4*>(
                &xb[(size_t)(k0 + 8 + brow) * NPIX + n0 + bcol]);
        }

#pragma unroll
        for (int kk = 0; kk < 8; kk++) {
            float a[8];
#pragma unroll
            for (int i = 0; i < 8; i++) a[i] = As[kk][ty * 8 + i];
            unsigned long long b2[4];
            const unsigned long long* bp =
                reinterpret_cast<const unsigned long long*>(&Bs[kk][tx * 8]);
#pragma unroll
            for (int j = 0; j < 4; j++) b2[j] = bp[j];
#pragma unroll
            for (int i = 0; i < 8; i++) {
                unsigned long long a2 = pack2(a[i], a[i]);
#pragma unroll
                for (int j = 0; j < 4; j++) acc[i][j] = ffma2(a2, b2[j], acc[i][j]);
            }
        }
    }

    // epilogue: section 0=q(elu1), 1=k(elu1 * (1+cs*cm)), 2=v(copy)
    const int sec = o0 / HIDD;
    const int obase = (o0 % HIDD) + ty * 8;
    const float cs = *csp;
    const float* cmb = cm + (size_t)b * NPIX;
    float* dst = (sec == 0) ? g_q : (sec == 1) ? g_k : g_v;
    const int ng = n0 + tx * 8;

    float cmv[8];
    if (sec == 1) {
#pragma unroll
        for (int j = 0; j < 8; j++) cmv[j] = 1.0f + cs * cmb[ng + j];
    }

#pragma unroll
    for (int i = 0; i < 8; i++) {
        float vals[8];
#pragma unroll
        for (int jp = 0; jp < 4; jp++) unpack2(acc[i][jp], vals[2 * jp], vals[2 * jp + 1]);
        if (sec == 0) {
#pragma unroll
            for (int j = 0; j < 8; j++) vals[j] = elu1f(vals[j]);
        } else if (sec == 1) {
#pragma unroll
            for (int j = 0; j < 8; j++) vals[j] = elu1f(vals[j]) * cmv[j];
        }
        float* p = &dst[((size_t)b * HIDD + obase + i) * NPIX + ng];
        float4 lo, hi;
        lo.x = vals[0]; lo.y = vals[1]; lo.z = vals[2]; lo.w = vals[3];
        hi.x = vals[4]; hi.y = vals[5]; hi.z = vals[6]; hi.w = vals[7];
        *reinterpret_cast<float4*>(p)     = lo;
        *reinterpret_cast<float4*>(p + 4) = hi;
    }
}

// ============================================================================
// Kernel 2: per (b,h): kv[d,e] = sum_n k[d,n]*v[e,n]; ksum[d] = sum_n k[d,n].
// Grid (8 n-splits, 64 bh); atomic accumulation into zeroed g_kv/g_ksum.
// ============================================================================
__global__ __launch_bounds__(256) void kv_ksum_kernel()
{
    __shared__ float ks[64][65];
    __shared__ float vs[64][65];

    const int bh    = blockIdx.y;
    const int split = blockIdx.x;
    const int tid = threadIdx.x;
    const int td = tid >> 4, te = tid & 15;

    const float* kbase = g_k + (size_t)bh * DHEAD * NPIX;
    const float* vbase = g_v + (size_t)bh * DHEAD * NPIX;

    float acc[4][4] = {};
    float myksum = 0.0f;

    for (int c = 0; c < 8; c++) {
        const int n0 = split * 512 + c * 64;
        __syncthreads();
        for (int f = tid; f < 1024; f += 256) {
            const int row = f >> 4, col = (f & 15) * 4;
            float4 k4 = *reinterpret_cast<const float4*>(&kbase[(size_t)row * NPIX + n0 + col]);
            ks[row][col + 0] = k4.x; ks[row][col + 1] = k4.y;
            ks[row][col + 2] = k4.z; ks[row][col + 3] = k4.w;
            float4 v4 = *reinterpret_cast<const float4*>(&vbase[(size_t)row * NPIX + n0 + col]);
            vs[row][col + 0] = v4.x; vs[row][col + 1] = v4.y;
            vs[row][col + 2] = v4.z; vs[row][col + 3] = v4.w;
        }
        __syncthreads();

#pragma unroll 4
        for (int nn = 0; nn < 64; nn++) {
            float kf[4], vf[4];
#pragma unroll
            for (int i = 0; i < 4; i++) kf[i] = ks[td * 4 + i][nn];
#pragma unroll
            for (int j = 0; j < 4; j++) vf[j] = vs[te * 4 + j][nn];
#pragma unroll
            for (int i = 0; i < 4; i++)
#pragma unroll
                for (int j = 0; j < 4; j++) acc[i][j] = fmaf(kf[i], vf[j], acc[i][j]);
        }
        if (tid < 64) {
            float s = 0.0f;
#pragma unroll 8
            for (int nn = 0; nn < 64; nn++) s += ks[tid][nn];
            myksum += s;
        }
    }

    float* kvout = g_kv + (size_t)bh * DHEAD * DHEAD;
#pragma unroll
    for (int i = 0; i < 4; i++)
#pragma unroll
        for (int j = 0; j < 4; j++)
            atomicAdd(&kvout[(td * 4 + i) * DHEAD + te * 4 + j], acc[i][j]);
    if (tid < 64) atomicAdd(&g_ksum[bh * DHEAD + tid], myksum);
}

// ============================================================================
// Kernel 3: out2[b, h*64+e, n] = (sum_d kv[d,e]*q[d,n]) / (sum_d q[d,n]*ksum[d] + 1e-6)
// Grid (64 n-chunks, 64 bh).
// ============================================================================
__global__ __launch_bounds__(256) void attn_out_kernel()
{
    __shared__ float qs[64][65];
    __shared__ float kvs[64][65];
    __shared__ float ksum_s[64];
    __shared__ float zs[64];

    const int bh = blockIdx.y;
    const int n0 = blockIdx.x * 64;
    const int tid = threadIdx.x;

    const float* qbase = g_q + (size_t)bh * DHEAD * NPIX;
    const float* kvbase = g_kv + (size_t)bh * DHEAD * DHEAD;

    for (int f = tid; f < 1024; f += 256) {
        const int row = f >> 4, col = (f & 15) * 4;
        float4 q4 = *reinterpret_cast<const float4*>(&qbase[(size_t)row * NPIX + n0 + col]);
        qs[row][col + 0] = q4.x; qs[row][col + 1] = q4.y;
        qs[row][col + 2] = q4.z; qs[row][col + 3] = q4.w;
        float4 k4 = *reinterpret_cast<const float4*>(&kvbase[f * 4]);
        kvs[row][col + 0] = k4.x; kvs[row][col + 1] = k4.y;
        kvs[row][col + 2] = k4.z; kvs[row][col + 3] = k4.w;
    }
    if (tid < 64) ksum_s[tid] = g_ksum[bh * DHEAD + tid];
    __syncthreads();

    if (tid < 64) {
        float den = 1e-6f;
#pragma unroll 8
        for (int d = 0; d < 64; d++) den = fmaf(qs[d][tid], ksum_s[d], den);
        zs[tid] = 1.0f / den;
    }
    __syncthreads();

    const int tn = tid & 15, te = tid >> 4;
    float acc[4][4] = {};
#pragma unroll 4
    for (int d = 0; d < 64; d++) {
        float qf[4], kf[4];
#pragma unroll
        for (int j = 0; j < 4; j++) qf[j] = qs[d][tn * 4 + j];
#pragma unroll
        for (int i = 0; i < 4; i++) kf[i] = kvs[d][te * 4 + i];
#pragma unroll
        for (int i = 0; i < 4; i++)
#pragma unroll
            for (int j = 0; j < 4; j++) acc[i][j] = fmaf(kf[i], qf[j], acc[i][j]);
    }

    float* obase = g_out2 + (size_t)bh * DHEAD * NPIX;
    float zv[4];
#pragma unroll
    for (int j = 0; j < 4; j++) zv[j] = zs[tn * 4 + j];
#pragma unroll
    for (int i = 0; i < 4; i++) {
        float4 w;
        w.x = acc[i][0] * zv[0]; w.y = acc[i][1] * zv[1];
        w.z = acc[i][2] * zv[2]; w.w = acc[i][3] * zv[3];
        *reinterpret_cast<float4*>(&obase[(size_t)(te * 4 + i) * NPIX + n0 + tn * 4]) = w;
    }
}

// ============================================================================
// Kernel 4: y = Wout[256,512] @ out2[b][512,4096] + bout  (same SGEMM scheme)
// ============================================================================
__global__ __launch_bounds__(256) void out_gemm_kernel(
    const float* __restrict__ Wout, const float* __restrict__ bout,
    float* __restrict__ y)
{
    __shared__ float As[8][132];
    __shared__ float Bs[8][128];

    const int b  = blockIdx.z;
    const int o0 = blockIdx.y * 128;
    const int n0 = blockIdx.x * 128;
    const int tid = threadIdx.x;
    const int tx = tid & 15;
    const int ty = tid >> 4;

    const float* xb = g_out2 + (size_t)b * HIDD * NPIX;

    unsigned long long acc[8][4];
#pragma unroll
    for (int i = 0; i < 8; i++)
#pragma unroll
        for (int j = 0; j < 4; j++) acc[i][j] = 0ULL;

    const int arow = tid >> 1, ahalf = tid & 1;
    const int brow = tid >> 5, bcol = (tid & 31) * 4;

    float4 av = *reinterpret_cast<const float4*>(
        &Wout[(size_t)(o0 + arow) * HIDD + 0 + ahalf * 4]);
    float4 bv = *reinterpret_cast<const float4*>(
        &xb[(size_t)(0 + brow) * NPIX + n0 + bcol]);

    for (int k0 = 0; k0 < HIDD; k0 += 8) {
        __syncthreads();
        As[ahalf * 4 + 0][arow] = av.x;
        As[ahalf * 4 + 1][arow] = av.y;
        As[ahalf * 4 + 2][arow] = av.z;
        As[ahalf * 4 + 3][arow] = av.w;
        *reinterpret_cast<float4*>(&Bs[brow][bcol]) = bv;
        __syncthreads();

        if (k0 + 8 < HIDD) {
            av = *reinterpret_cast<const float4*>(
                &Wout[(size_t)(o0 + arow) * HIDD + (k0 + 8) + ahalf * 4]);
            bv = *reinterpret_cast<const float4*>(
                &xb[(size_t)(k0 + 8 + brow) * NPIX + n0 + bcol]);
        }

#pragma unroll
        for (int kk = 0; kk < 8; kk++) {
            float a[8];
#pragma unroll
            for (int i = 0; i < 8; i++) a[i] = As[kk][ty * 8 + i];
            unsigned long long b2[4];
            const unsigned long long* bp =
                reinterpret_cast<const unsigned long long*>(&Bs[kk][tx * 8]);
#pragma unroll
            for (int j = 0; j < 4; j++) b2[j] = bp[j];
#pragma unroll
            for (int i = 0; i < 8; i++) {
                unsigned long long a2 = pack2(a[i], a[i]);
#pragma unroll
                for (int j = 0; j < 4; j++) acc[i][j] = ffma2(a2, b2[j], acc[i][j]);
            }
        }
    }

    const int ng = n0 + tx * 8;
#pragma unroll
    for (int i = 0; i < 8; i++) {
        const int oo = o0 + ty * 8 + i;
        const float bo = bout[oo];
        float vals[8];
#pragma unroll
        for (int jp = 0; jp < 4; jp++) unpack2(acc[i][jp], vals[2 * jp], vals[2 * jp + 1]);
#pragma unroll
        for (int j = 0; j < 8; j++) vals[j] += bo;
        float* p = &y[((size_t)b * CDIM + oo) * NPIX + ng];
        float4 lo, hi;
        lo.x = vals[0]; lo.y = vals[1]; lo.z = vals[2]; lo.w = vals[3];
        hi.x = vals[4]; hi.y = vals[5]; hi.z = vals[6]; hi.w = vals[7];
        *reinterpret_cast<float4*>(p)     = lo;
        *reinterpret_cast<float4*>(p + 4) = hi;
    }
}

// ============================================================================
extern "C" void kernel_launch(void* const* d_in, const int* in_sizes, int n_in,
                              void* d_out, int out_size)
{
    const float* x    = (const float*)d_in[0];
    const float* cm   = (const float*)d_in[1];
    const float* Wqkv = (const float*)d_in[2];
    const float* Wout = (const float*)d_in[3];
    const float* bout = (const float*)d_in[4];
    const float* cs   = (const float*)d_in[5];
    float* y = (float*)d_out;

    void *kvp = nullptr, *ksp = nullptr;
    cudaGetSymbolAddress(&kvp, g_kv);
    cudaGetSymbolAddress(&ksp, g_ksum);
    cudaMemsetAsync(kvp, 0, sizeof(float) * BATCH * NHEAD * DHEAD * DHEAD);
    cudaMemsetAsync(ksp, 0, sizeof(float) * BATCH * NHEAD * DHEAD);

    qkv_gemm_kernel<<<dim3(NPIX / 128, O1 / 128, BATCH), 256>>>(x, Wqkv, cm, cs);
    kv_ksum_kernel<<<dim3(8, BATCH * NHEAD), 256>>>();
    attn_out_kernel<<<dim3(NPIX / 64, BATCH * NHEAD), 256>>>();
    out_gemm_kernel<<<dim3(NPIX / 128, CDIM / 128, BATCH), 256>>>(Wout, bout, y);
}

// round 3
// speedup vs baseline: 2.0447x; 2.0447x over previous
#include <cuda_runtime.h>
#include <cstdint>
#include <cstddef>

#define BATCH 8
#define CDIM  256
#define NPIX  4096
#define O1    1536
#define HIDD  512
#define NHEAD 8
#define DHEAD 64

// ---------------- scratch (device globals; no allocation allowed) ----------
__device__ float g_q[BATCH * HIDD * NPIX];
__device__ float g_k[BATCH * HIDD * NPIX];
__device__ float g_v[BATCH * HIDD * NPIX];
__device__ float g_out2[BATCH * HIDD * NPIX];
__device__ float g_kv[BATCH * NHEAD * DHEAD * DHEAD];
__device__ float g_ksum[BATCH * NHEAD * DHEAD];

// ---------------- helpers ---------------------------------------------------
__device__ __forceinline__ uint32_t f2tf32(float f) {
    uint32_t r;
    asm("cvt.rna.tf32.f32 %0, %1;" : "=r"(r) : "f"(f));
    return r;
}
__device__ __forceinline__ float elu1f(float x) {
    return x > 0.0f ? x + 1.0f : expf(x);
}
__device__ __forceinline__ void mma_tf32(float c[4], const uint32_t a[4],
                                         const uint32_t b[2]) {
    asm volatile(
        "mma.sync.aligned.m16n8k8.row.col.f32.tf32.tf32.f32 "
        "{%0,%1,%2,%3}, {%4,%5,%6,%7}, {%8,%9}, {%0,%1,%2,%3};"
        : "+f"(c[0]), "+f"(c[1]), "+f"(c[2]), "+f"(c[3])
        : "r"(a[0]), "r"(a[1]), "r"(a[2]), "r"(a[3]), "r"(b[0]), "r"(b[1]));
}

// ===================== tf32 tensor-core GEMM machinery ======================
// CTA tile 128(M) x 128(N), K-chunk 32, double-buffered smem.
// A smem: [128 m][k stride 36]  -> banks (4m + k) % 32: conflict-free
// B smem: [32 k][n stride 136]  -> banks (8k + n) % 32: conflict-free
#define A_STRIDE 36
#define B_STRIDE 136
#define A_ELEMS (128 * A_STRIDE)          // 4608 floats
#define BUF_ELEMS (A_ELEMS + 32 * B_STRIDE) // + 4352 = 8960 floats
#define SMEM_BYTES (2 * BUF_ELEMS * 4)    // 71680 bytes

// Per-thread fragment state: acc[2 mt][8 nt][4]
struct Frag { float c[2][8][4]; };

// Stage one K-chunk from gmem into regs (8 float4 per thread).
struct Pref { float4 a[4]; float4 b[4]; };

__device__ __forceinline__ void pref_load(
    Pref& p, const float* __restrict__ A, int lda,
    const float* __restrict__ B, int ldb, int o0, int n0, int k0, int tid)
{
#pragma unroll
    for (int i = 0; i < 4; ++i) {
        const int fi = tid + i * 256;                // [0,1024)
        const int row = fi >> 3, c4 = (fi & 7) * 4;  // A: 128 x 32
        p.a[i] = *reinterpret_cast<const float4*>(&A[(size_t)(o0 + row) * lda + k0 + c4]);
    }
#pragma unroll
    for (int i = 0; i < 4; ++i) {
        const int fi = tid + i * 256;
        const int row = fi >> 5, c4 = (fi & 31) * 4; // B: 32 x 128
        p.b[i] = *reinterpret_cast<const float4*>(&B[(size_t)(k0 + row) * ldb + n0 + c4]);
    }
}

__device__ __forceinline__ void pref_store(const Pref& p, uint32_t* sm_u, int tid)
{
    uint32_t* As = sm_u;
    uint32_t* Bs = sm_u + A_ELEMS;
#pragma unroll
    for (int i = 0; i < 4; ++i) {
        const int fi = tid + i * 256;
        const int row = fi >> 3, c4 = (fi & 7) * 4;
        uint4 t;
        t.x = f2tf32(p.a[i].x); t.y = f2tf32(p.a[i].y);
        t.z = f2tf32(p.a[i].z); t.w = f2tf32(p.a[i].w);
        *reinterpret_cast<uint4*>(&As[row * A_STRIDE + c4]) = t;
    }
#pragma unroll
    for (int i = 0; i < 4; ++i) {
        const int fi = tid + i * 256;
        const int row = fi >> 5, c4 = (fi & 31) * 4;
        uint4 t;
        t.x = f2tf32(p.b[i].x); t.y = f2tf32(p.b[i].y);
        t.z = f2tf32(p.b[i].z); t.w = f2tf32(p.b[i].w);
        *reinterpret_cast<uint4*>(&Bs[row * B_STRIDE + c4]) = t;
    }
}

__device__ __forceinline__ void chunk_mma(
    Frag& fr, const uint32_t* sm_u, int warp_m, int warp_n, int lq, int kq)
{
    const uint32_t* As = sm_u;
    const uint32_t* Bs = sm_u + A_ELEMS;
#pragma unroll
    for (int ks = 0; ks < 4; ++ks) {
        const int kb = ks * 8 + kq;
        uint32_t a[2][4];
#pragma unroll
        for (int mt = 0; mt < 2; ++mt) {
            const int m = warp_m + mt * 16 + lq;
            a[mt][0] = As[m * A_STRIDE + kb];
            a[mt][1] = As[(m + 8) * A_STRIDE + kb];
            a[mt][2] = As[m * A_STRIDE + kb + 4];
            a[mt][3] = As[(m + 8) * A_STRIDE + kb + 4];
        }
        uint32_t bfr[8][2];
#pragma unroll
        for (int nt = 0; nt < 8; ++nt) {
            const int n = warp_n + nt * 8 + lq;
            bfr[nt][0] = Bs[kb * B_STRIDE + n];
            bfr[nt][1] = Bs[(kb + 4) * B_STRIDE + n];
        }
#pragma unroll
        for (int mt = 0; mt < 2; ++mt)
#pragma unroll
            for (int nt = 0; nt < 8; ++nt)
                mma_tf32(fr.c[mt][nt], a[mt], bfr[nt]);
    }
}

// Full mainloop: result left in fr.
__device__ __forceinline__ void gemm_mainloop(
    Frag& fr, const float* __restrict__ A, int lda,
    const float* __restrict__ B, int ldb,
    int o0, int n0, int K, uint32_t* sm_u)
{
    const int tid = threadIdx.x;
    const int wid = tid >> 5, lane = tid & 31;
    const int warp_m = (wid & 3) * 32;
    const int warp_n = (wid >> 2) * 64;
    const int lq = lane >> 2, kq = lane & 3;
    const int NC = K / 32;

#pragma unroll
    for (int mt = 0; mt < 2; ++mt)
#pragma unroll
        for (int nt = 0; nt < 8; ++nt)
#pragma unroll
            for (int i = 0; i < 4; ++i) fr.c[mt][nt][i] = 0.0f;

    Pref p;
    pref_load(p, A, lda, B, ldb, o0, n0, 0, tid);
    pref_store(p, sm_u, tid);
    __syncthreads();

    for (int c = 0; c < NC; ++c) {
        const int cur = c & 1;
        if (c + 1 < NC)
            pref_load(p, A, lda, B, ldb, o0, n0, (c + 1) * 32, tid);
        chunk_mma(fr, sm_u + cur * BUF_ELEMS, warp_m, warp_n, lq, kq);
        if (c + 1 < NC) {
            pref_store(p, sm_u + (cur ^ 1) * BUF_ELEMS, tid);
            __syncthreads();
        }
    }
}

// ============================================================================
// Kernel 1: qkv = Wqkv[1536,256] @ x[b][256,4096], fused elu1 + contact scale.
// ============================================================================
__global__ __launch_bounds__(256) void qkv_mma_kernel(
    const float* __restrict__ x, const float* __restrict__ Wqkv,
    const float* __restrict__ cm, const float* __restrict__ csp)
{
    extern __shared__ uint32_t sm_u[];
    const int b  = blockIdx.z;
    const int o0 = blockIdx.y * 128;
    const int n0 = blockIdx.x * 128;

    Frag fr;
    gemm_mainloop(fr, Wqkv, CDIM, x + (size_t)b * CDIM * NPIX, NPIX,
                  o0, n0, CDIM, sm_u);

    const int tid = threadIdx.x;
    const int wid = tid >> 5, lane = tid & 31;
    const int warp_m = (wid & 3) * 32;
    const int warp_n = (wid >> 2) * 64;
    const int lq = lane >> 2, kq = lane & 3;

    const int sec = o0 >> 9;                 // 0=q, 1=k, 2=v
    const int obase = o0 & 511;
    float* dst = (sec == 0) ? g_q : (sec == 1) ? g_k : g_v;
    const float cs = (sec == 1) ? *csp : 0.0f;
    const float* cmb = cm + (size_t)b * NPIX;

#pragma unroll
    for (int nt = 0; nt < 8; ++nt) {
        const int cg = n0 + warp_n + nt * 8 + kq * 2;
        float m0 = 1.0f, m1 = 1.0f;
        if (sec == 1) {
            m0 = 1.0f + cs * cmb[cg];
            m1 = 1.0f + cs * cmb[cg + 1];
        }
#pragma unroll
        for (int mt = 0; mt < 2; ++mt) {
            const int rl = warp_m + mt * 16 + lq;
#pragma unroll
            for (int ri = 0; ri < 2; ++ri) {
                const int grow = obase + rl + ri * 8;
                float v0 = fr.c[mt][nt][2 * ri + 0];
                float v1 = fr.c[mt][nt][2 * ri + 1];
                if (sec == 0)      { v0 = elu1f(v0);       v1 = elu1f(v1); }
                else if (sec == 1) { v0 = elu1f(v0) * m0;  v1 = elu1f(v1) * m1; }
                float2 w; w.x = v0; w.y = v1;
                *reinterpret_cast<float2*>(
                    &dst[((size_t)b * HIDD + grow) * NPIX + cg]) = w;
            }
        }
    }
}

// ============================================================================
// Kernel 4: y = Wout[256,512] @ out2[b][512,4096] + bout
// ============================================================================
__global__ __launch_bounds__(256) void out_mma_kernel(
    const float* __restrict__ Wout, const float* __restrict__ bout,
    float* __restrict__ y)
{
    extern __shared__ uint32_t sm_u[];
    const int b  = blockIdx.z;
    const int o0 = blockIdx.y * 128;
    const int n0 = blockIdx.x * 128;

    Frag fr;
    gemm_mainloop(fr, Wout, HIDD, g_out2 + (size_t)b * HIDD * NPIX, NPIX,
                  o0, n0, HIDD, sm_u);

    const int tid = threadIdx.x;
    const int wid = tid >> 5, lane = tid & 31;
    const int warp_m = (wid & 3) * 32;
    const int warp_n = (wid >> 2) * 64;
    const int lq = lane >> 2, kq = lane & 3;

#pragma unroll
    for (int mt = 0; mt < 2; ++mt) {
        const int rl = warp_m + mt * 16 + lq;
#pragma unroll
        for (int ri = 0; ri < 2; ++ri) {
            const int grow = o0 + rl + ri * 8;
            const float bo = bout[grow];
#pragma unroll
            for (int nt = 0; nt < 8; ++nt) {
                const int cg = n0 + warp_n + nt * 8 + kq * 2;
                float2 w;
                w.x = fr.c[mt][nt][2 * ri + 0] + bo;
                w.y = fr.c[mt][nt][2 * ri + 1] + bo;
                *reinterpret_cast<float2*>(
                    &y[((size_t)b * CDIM + grow) * NPIX + cg]) = w;
            }
        }
    }
}

// ============================================================================
// Kernel 2: per (b,h): kv[d,e] = sum_n k[d,n]*v[e,n]; ksum[d] = sum_n k[d,n].
// ============================================================================
__global__ __launch_bounds__(256) void kv_ksum_kernel()
{
    __shared__ float ks[64][65];
    __shared__ float vs[64][65];

    const int bh    = blockIdx.y;
    const int split = blockIdx.x;
    const int tid = threadIdx.x;
    const int td = tid >> 4, te = tid & 15;

    const float* kbase = g_k + (size_t)bh * DHEAD * NPIX;
    const float* vbase = g_v + (size_t)bh * DHEAD * NPIX;

    float acc[4][4] = {};
    float myksum = 0.0f;

    for (int c = 0; c < 8; c++) {
        const int n0 = split * 512 + c * 64;
        __syncthreads();
        for (int f = tid; f < 1024; f += 256) {
            const int row = f >> 4, col = (f & 15) * 4;
            float4 k4 = *reinterpret_cast<const float4*>(&kbase[(size_t)row * NPIX + n0 + col]);
            ks[row][col + 0] = k4.x; ks[row][col + 1] = k4.y;
            ks[row][col + 2] = k4.z; ks[row][col + 3] = k4.w;
            float4 v4 = *reinterpret_cast<const float4*>(&vbase[(size_t)row * NPIX + n0 + col]);
            vs[row][col + 0] = v4.x; vs[row][col + 1] = v4.y;
            vs[row][col + 2] = v4.z; vs[row][col + 3] = v4.w;
        }
        __syncthreads();

#pragma unroll 4
        for (int nn = 0; nn < 64; nn++) {
            float kf[4], vf[4];
#pragma unroll
            for (int i = 0; i < 4; i++) kf[i] = ks[td * 4 + i][nn];
#pragma unroll
            for (int j = 0; j < 4; j++) vf[j] = vs[te * 4 + j][nn];
#pragma unroll
            for (int i = 0; i < 4; i++)
#pragma unroll
                for (int j = 0; j < 4; j++) acc[i][j] = fmaf(kf[i], vf[j], acc[i][j]);
        }
        if (tid < 64) {
            float s = 0.0f;
#pragma unroll 8
            for (int nn = 0; nn < 64; nn++) s += ks[tid][nn];
            myksum += s;
        }
    }

    float* kvout = g_kv + (size_t)bh * DHEAD * DHEAD;
#pragma unroll
    for (int i = 0; i < 4; i++)
#pragma unroll
        for (int j = 0; j < 4; j++)
            atomicAdd(&kvout[(td * 4 + i) * DHEAD + te * 4 + j], acc[i][j]);
    if (tid < 64) atomicAdd(&g_ksum[bh * DHEAD + tid], myksum);
}

// ============================================================================
// Kernel 3: out2 = (kv^T q) * z
// ============================================================================
__global__ __launch_bounds__(256) void attn_out_kernel()
{
    __shared__ float qs[64][65];
    __shared__ float kvs[64][65];
    __shared__ float ksum_s[64];
    __shared__ float zs[64];

    const int bh = blockIdx.y;
    const int n0 = blockIdx.x * 64;
    const int tid = threadIdx.x;

    const float* qbase = g_q + (size_t)bh * DHEAD * NPIX;
    const float* kvbase = g_kv + (size_t)bh * DHEAD * DHEAD;

    for (int f = tid; f < 1024; f += 256) {
        const int row = f >> 4, col = (f & 15) * 4;
        float4 q4 = *reinterpret_cast<const float4*>(&qbase[(size_t)row * NPIX + n0 + col]);
        qs[row][col + 0] = q4.x; qs[row][col + 1] = q4.y;
        qs[row][col + 2] = q4.z; qs[row][col + 3] = q4.w;
        float4 k4 = *reinterpret_cast<const float4*>(&kvbase[f * 4]);
        kvs[row][col + 0] = k4.x; kvs[row][col + 1] = k4.y;
        kvs[row][col + 2] = k4.z; kvs[row][col + 3] = k4.w;
    }
    if (tid < 64) ksum_s[tid] = g_ksum[bh * DHEAD + tid];
    __syncthreads();

    if (tid < 64) {
        float den = 1e-6f;
#pragma unroll 8
        for (int d = 0; d < 64; d++) den = fmaf(qs[d][tid], ksum_s[d], den);
        zs[tid] = 1.0f / den;
    }
    __syncthreads();

    const int tn = tid & 15, te = tid >> 4;
    float acc[4][4] = {};
#pragma unroll 4
    for (int d = 0; d < 64; d++) {
        float qf[4], kf[4];
#pragma unroll
        for (int j = 0; j < 4; j++) qf[j] = qs[d][tn * 4 + j];
#pragma unroll
        for (int i = 0; i < 4; i++) kf[i] = kvs[d][te * 4 + i];
#pragma unroll
        for (int i = 0; i < 4; i++)
#pragma unroll
            for (int j = 0; j < 4; j++) acc[i][j] = fmaf(kf[i], qf[j], acc[i][j]);
    }

    float* obase = g_out2 + (size_t)bh * DHEAD * NPIX;
    float zv[4];
#pragma unroll
    for (int j = 0; j < 4; j++) zv[j] = zs[tn * 4 + j];
#pragma unroll
    for (int i = 0; i < 4; i++) {
        float4 w;
        w.x = acc[i][0] * zv[0]; w.y = acc[i][1] * zv[1];
        w.z = acc[i][2] * zv[2]; w.w = acc[i][3] * zv[3];
        *reinterpret_cast<float4*>(&obase[(size_t)(te * 4 + i) * NPIX + n0 + tn * 4]) = w;
    }
}

// ============================================================================
extern "C" void kernel_launch(void* const* d_in, const int* in_sizes, int n_in,
                              void* d_out, int out_size)
{
    const float* x    = (const float*)d_in[0];
    const float* cm   = (const float*)d_in[1];
    const float* Wqkv = (const float*)d_in[2];
    const float* Wout = (const float*)d_in[3];
    const float* bout = (const float*)d_in[4];
    const float* cs   = (const float*)d_in[5];
    float* y = (float*)d_out;

    static bool configured = false;
    if (!configured) {
        cudaFuncSetAttribute(qkv_mma_kernel,
                             cudaFuncAttributeMaxDynamicSharedMemorySize, SMEM_BYTES);
        cudaFuncSetAttribute(out_mma_kernel,
                             cudaFuncAttributeMaxDynamicSharedMemorySize, SMEM_BYTES);
        configured = true;
    }

    void *kvp = nullptr, *ksp = nullptr;
    cudaGetSymbolAddress(&kvp, g_kv);
    cudaGetSymbolAddress(&ksp, g_ksum);
    cudaMemsetAsync(kvp, 0, sizeof(float) * BATCH * NHEAD * DHEAD * DHEAD);
    cudaMemsetAsync(ksp, 0, sizeof(float) * BATCH * NHEAD * DHEAD);

    qkv_mma_kernel<<<dim3(NPIX / 128, O1 / 128, BATCH), 256, SMEM_BYTES>>>(x, Wqkv, cm, cs);
    kv_ksum_kernel<<<dim3(8, BATCH * NHEAD), 256>>>();
    attn_out_kernel<<<dim3(NPIX / 64, BATCH * NHEAD), 256>>>();
    out_mma_kernel<<<dim3(NPIX / 128, CDIM / 128, BATCH), 256, SMEM_BYTES>>>(Wout, bout, y);
}

// round 4
// speedup vs baseline: 2.2540x; 1.1023x over previous
#include <cuda_runtime.h>
#include <cstdint>
#include <cstddef>

#define BATCH 8
#define CDIM  256
#define NPIX  4096
#define O1    1536
#define HIDD  512
#define NHEAD 8
#define DHEAD 64

// ---------------- scratch (device globals; no allocation allowed) ----------
__device__ float g_q[BATCH * HIDD * NPIX];
__device__ float g_k[BATCH * HIDD * NPIX];
__device__ float g_v[BATCH * HIDD * NPIX];
__device__ float g_out2[BATCH * HIDD * NPIX];   // tf32-rounded by attn_out
__device__ float g_kv[BATCH * NHEAD * DHEAD * DHEAD];
__device__ float g_ksum[BATCH * NHEAD * DHEAD];
__device__ float g_x[BATCH * CDIM * NPIX];      // tf32-rounded x
__device__ float g_wq[O1 * CDIM];               // tf32-rounded Wqkv
__device__ float g_wo[CDIM * HIDD];             // tf32-rounded Wout

// ---------------- helpers ---------------------------------------------------
__device__ __forceinline__ uint32_t f2tf32(float f) {
    uint32_t r;
    asm("cvt.rna.tf32.f32 %0, %1;" : "=r"(r) : "f"(f));
    return r;
}
__device__ __forceinline__ float elu1f(float x) {
    return x > 0.0f ? x + 1.0f : expf(x);
}
__device__ __forceinline__ void mma_tf32(float c[4], const uint32_t a[4],
                                         const uint32_t b[2]) {
    asm volatile(
        "mma.sync.aligned.m16n8k8.row.col.f32.tf32.tf32.f32 "
        "{%0,%1,%2,%3}, {%4,%5,%6,%7}, {%8,%9}, {%0,%1,%2,%3};"
        : "+f"(c[0]), "+f"(c[1]), "+f"(c[2]), "+f"(c[3])
        : "r"(a[0]), "r"(a[1]), "r"(a[2]), "r"(a[3]), "r"(b[0]), "r"(b[1]));
}
__device__ __forceinline__ unsigned long long pack2(float lo, float hi) {
    unsigned long long r;
    asm("mov.b64 %0, {%1, %2};" : "=l"(r) : "f"(lo), "f"(hi));
    return r;
}
__device__ __forceinline__ void unpack2(unsigned long long v, float& lo, float& hi) {
    asm("mov.b64 {%0, %1}, %2;" : "=f"(lo), "=f"(hi) : "l"(v));
}
__device__ __forceinline__ unsigned long long ffma2(unsigned long long a,
                                                    unsigned long long b,
                                                    unsigned long long c) {
    unsigned long long d;
    asm("fma.rn.f32x2 %0, %1, %2, %3;" : "=l"(d) : "l"(a), "l"(b), "l"(c));
    return d;
}
__device__ __forceinline__ unsigned long long add2(unsigned long long a,
                                                   unsigned long long b) {
    unsigned long long d;
    asm("add.rn.f32x2 %0, %1, %2;" : "=l"(d) : "l"(a), "l"(b));
    return d;
}
__device__ __forceinline__ void cp_async16(uint32_t dst, const void* src) {
    asm volatile("cp.async.cg.shared.global [%0], [%1], 16;" :: "r"(dst), "l"(src));
}
__device__ __forceinline__ void cp_commit() {
    asm volatile("cp.async.commit_group;");
}
template <int N> __device__ __forceinline__ void cp_wait() {
    asm volatile("cp.async.wait_group %0;" :: "n"(N));
}

// ===================== tf32 tensor-core GEMM machinery ======================
// CTA tile 128(M) x 128(N), K-chunk 32, 3-stage cp.async ring buffer.
// A smem: [128 m][k stride 36]  -> conflict-free scalar loads
// B smem: [32 k][n stride 136]  -> conflict-free scalar loads
#define A_STRIDE 36
#define B_STRIDE 136
#define A_ELEMS (128 * A_STRIDE)              // 4608
#define B_ELEMS (32 * B_STRIDE)               // 4352
#define BUF_ELEMS (A_ELEMS + B_ELEMS)         // 8960
#define BUF_BYTES (BUF_ELEMS * 4)             // 35840
#define NSTAGE 3
#define SMEM_BYTES (NSTAGE * BUF_BYTES)       // 107520

struct Frag { float c[2][8][4]; };

// One K-chunk gmem->smem via cp.async (8 x 16B per thread), then commit.
__device__ __forceinline__ void stage_cp(
    uint32_t sbase, const float* __restrict__ A, int lda,
    const float* __restrict__ B, int ldb, int o0, int n0, int k0, int tid)
{
    const uint32_t abase = sbase;
    const uint32_t bbase = sbase + A_ELEMS * 4;
#pragma unroll
    for (int i = 0; i < 4; ++i) {
        const int fi = tid + i * 256;
        const int row = fi >> 3, c4 = (fi & 7) * 4;
        cp_async16(abase + (uint32_t)(row * A_STRIDE + c4) * 4,
                   &A[(size_t)(o0 + row) * lda + k0 + c4]);
    }
#pragma unroll
    for (int i = 0; i < 4; ++i) {
        const int fi = tid + i * 256;
        const int row = fi >> 5, c4 = (fi & 31) * 4;
        cp_async16(bbase + (uint32_t)(row * B_STRIDE + c4) * 4,
                   &B[(size_t)(k0 + row) * ldb + n0 + c4]);
    }
    cp_commit();
}

__device__ __forceinline__ void chunk_mma(
    Frag& fr, const uint32_t* sm_u, int warp_m, int warp_n, int lq, int kq)
{
    const uint32_t* As = sm_u;
    const uint32_t* Bs = sm_u + A_ELEMS;
#pragma unroll
    for (int ks = 0; ks < 4; ++ks) {
        const int kb = ks * 8 + kq;
        uint32_t a[2][4];
#pragma unroll
        for (int mt = 0; mt < 2; ++mt) {
            const int m = warp_m + mt * 16 + lq;
            a[mt][0] = As[m * A_STRIDE + kb];
            a[mt][1] = As[(m + 8) * A_STRIDE + kb];
            a[mt][2] = As[m * A_STRIDE + kb + 4];
            a[mt][3] = As[(m + 8) * A_STRIDE + kb + 4];
        }
        uint32_t bfr[8][2];
#pragma unroll
        for (int nt = 0; nt < 8; ++nt) {
            const int n = warp_n + nt * 8 + lq;
            bfr[nt][0] = Bs[kb * B_STRIDE + n];
            bfr[nt][1] = Bs[(kb + 4) * B_STRIDE + n];
        }
#pragma unroll
        for (int mt = 0; mt < 2; ++mt)
#pragma unroll
            for (int nt = 0; nt < 8; ++nt)
                mma_tf32(fr.c[mt][nt], a[mt], bfr[nt]);
    }
}

__device__ __forceinline__ void gemm_mainloop(
    Frag& fr, const float* __restrict__ A, int lda,
    const float* __restrict__ B, int ldb,
    int o0, int n0, int K, uint32_t* sm_u)
{
    const int tid = threadIdx.x;
    const int wid = tid >> 5, lane = tid & 31;
    const int warp_m = (wid & 3) * 32;
    const int warp_n = (wid >> 2) * 64;
    const int lq = lane >> 2, kq = lane & 3;
    const int NC = K / 32;

    uint32_t sbase;
    asm("{ .reg .u64 t; cvta.to.shared.u64 t, %1; cvt.u32.u64 %0, t; }"
        : "=r"(sbase) : "l"(sm_u));

#pragma unroll
    for (int mt = 0; mt < 2; ++mt)
#pragma unroll
        for (int nt = 0; nt < 8; ++nt)
#pragma unroll
            for (int i = 0; i < 4; ++i) fr.c[mt][nt][i] = 0.0f;

    stage_cp(sbase, A, lda, B, ldb, o0, n0, 0, tid);
    stage_cp(sbase + BUF_BYTES, A, lda, B, ldb, o0, n0, 32, tid);

    for (int c = 0; c < NC; ++c) {
        if (c < NC - 1) cp_wait<1>(); else cp_wait<0>();
        __syncthreads();
        if (c + 2 < NC)
            stage_cp(sbase + (uint32_t)((c + 2) % 3) * BUF_BYTES,
                     A, lda, B, ldb, o0, n0, (c + 2) * 32, tid);
        chunk_mma(fr, sm_u + (size_t)(c % 3) * BUF_ELEMS, warp_m, warp_n, lq, kq);
    }
}

// ============================================================================
// Kernel 0: round x, Wqkv, Wout to tf32 into scratch.
// ============================================================================
#define NX4  (BATCH * CDIM * NPIX / 4)
#define NW14 (O1 * CDIM / 4)
#define NW24 (CDIM * HIDD / 4)

__global__ __launch_bounds__(256) void preconv_kernel(
    const float4* __restrict__ x, const float4* __restrict__ wq,
    const float4* __restrict__ wo)
{
    const int i = blockIdx.x * 256 + threadIdx.x;
    float4 v;
    uint4* dst;
    if (i < NX4) {
        v = x[i]; dst = reinterpret_cast<uint4*>(g_x) + i;
    } else if (i < NX4 + NW14) {
        v = wq[i - NX4]; dst = reinterpret_cast<uint4*>(g_wq) + (i - NX4);
    } else if (i < NX4 + NW14 + NW24) {
        v = wo[i - NX4 - NW14];
        dst = reinterpret_cast<uint4*>(g_wo) + (i - NX4 - NW14);
    } else {
        return;
    }
    uint4 t;
    t.x = f2tf32(v.x); t.y = f2tf32(v.y); t.z = f2tf32(v.z); t.w = f2tf32(v.w);
    *dst = t;
}

// ============================================================================
// Kernel 1: qkv = Wqkv[1536,256] @ x[b][256,4096], fused elu1 + contact scale.
// ============================================================================
__global__ __launch_bounds__(256, 2) void qkv_mma_kernel(
    const float* __restrict__ cm, const float* __restrict__ csp)
{
    extern __shared__ uint32_t sm_u[];
    const int b  = blockIdx.z;
    const int o0 = blockIdx.y * 128;
    const int n0 = blockIdx.x * 128;

    Frag fr;
    gemm_mainloop(fr, g_wq, CDIM, g_x + (size_t)b * CDIM * NPIX, NPIX,
                  o0, n0, CDIM, sm_u);

    const int tid = threadIdx.x;
    const int wid = tid >> 5, lane = tid & 31;
    const int warp_m = (wid & 3) * 32;
    const int warp_n = (wid >> 2) * 64;
    const int lq = lane >> 2, kq = lane & 3;

    const int sec = o0 >> 9;                 // 0=q, 1=k, 2=v
    const int obase = o0 & 511;
    float* dst = (sec == 0) ? g_q : (sec == 1) ? g_k : g_v;
    const float cs = (sec == 1) ? *csp : 0.0f;
    const float* cmb = cm + (size_t)b * NPIX;

#pragma unroll
    for (int nt = 0; nt < 8; ++nt) {
        const int cg = n0 + warp_n + nt * 8 + kq * 2;
        float m0 = 1.0f, m1 = 1.0f;
        if (sec == 1) {
            m0 = 1.0f + cs * cmb[cg];
            m1 = 1.0f + cs * cmb[cg + 1];
        }
#pragma unroll
        for (int mt = 0; mt < 2; ++mt) {
            const int rl = warp_m + mt * 16 + lq;
#pragma unroll
            for (int ri = 0; ri < 2; ++ri) {
                const int grow = obase + rl + ri * 8;
                float v0 = fr.c[mt][nt][2 * ri + 0];
                float v1 = fr.c[mt][nt][2 * ri + 1];
                if (sec == 0)      { v0 = elu1f(v0);       v1 = elu1f(v1); }
                else if (sec == 1) { v0 = elu1f(v0) * m0;  v1 = elu1f(v1) * m1; }
                float2 w; w.x = v0; w.y = v1;
                *reinterpret_cast<float2*>(
                    &dst[((size_t)b * HIDD + grow) * NPIX + cg]) = w;
            }
        }
    }
}

// ============================================================================
// Kernel 4: y = Wout[256,512] @ out2[b][512,4096] + bout
// ============================================================================
__global__ __launch_bounds__(256, 2) void out_mma_kernel(
    const float* __restrict__ bout, float* __restrict__ y)
{
    extern __shared__ uint32_t sm_u[];
    const int b  = blockIdx.z;
    const int o0 = blockIdx.y * 128;
    const int n0 = blockIdx.x * 128;

    Frag fr;
    gemm_mainloop(fr, g_wo, HIDD, g_out2 + (size_t)b * HIDD * NPIX, NPIX,
                  o0, n0, HIDD, sm_u);

    const int tid = threadIdx.x;
    const int wid = tid >> 5, lane = tid & 31;
    const int warp_m = (wid & 3) * 32;
    const int warp_n = (wid >> 2) * 64;
    const int lq = lane >> 2, kq = lane & 3;

#pragma unroll
    for (int mt = 0; mt < 2; ++mt) {
        const int rl = warp_m + mt * 16 + lq;
#pragma unroll
        for (int ri = 0; ri < 2; ++ri) {
            const int grow = o0 + rl + ri * 8;
            const float bo = bout[grow];
#pragma unroll
            for (int nt = 0; nt < 8; ++nt) {
                const int cg = n0 + warp_n + nt * 8 + kq * 2;
                float2 w;
                w.x = fr.c[mt][nt][2 * ri + 0] + bo;
                w.y = fr.c[mt][nt][2 * ri + 1] + bo;
                *reinterpret_cast<float2*>(
                    &y[((size_t)b * CDIM + grow) * NPIX + cg]) = w;
            }
        }
    }
}

// ============================================================================
// Kernel 2: per (b,h): kv[d,e] = sum_n k[d,n]*v[e,n]; ksum[d] = sum_n k[d,n].
// f32x2 packed over (n, n+1); micro-tile d = td+16i, e = te+16j.
// ============================================================================
__global__ __launch_bounds__(256) void kv_ksum_kernel()
{
    __shared__ float ks[64][68];
    __shared__ float vs[64][68];

    const int bh    = blockIdx.y;
    const int split = blockIdx.x;
    const int tid = threadIdx.x;
    const int td = tid >> 4, te = tid & 15;

    const float* kbase = g_k + (size_t)bh * DHEAD * NPIX;
    const float* vbase = g_v + (size_t)bh * DHEAD * NPIX;

    unsigned long long acc2[4][4];
#pragma unroll
    for (int i = 0; i < 4; ++i)
#pragma unroll
        for (int j = 0; j < 4; ++j) acc2[i][j] = 0ULL;
    unsigned long long ksum2 = 0ULL;

    for (int c = 0; c < 8; c++) {
        const int n0 = split * 512 + c * 64;
        __syncthreads();
        for (int f = tid; f < 1024; f += 256) {
            const int row = f >> 4, col = (f & 15) * 4;
            float4 k4 = *reinterpret_cast<const float4*>(&kbase[(size_t)row * NPIX + n0 + col]);
            *reinterpret_cast<float4*>(&ks[row][col]) = k4;
            float4 v4 = *reinterpret_cast<const float4*>(&vbase[(size_t)row * NPIX + n0 + col]);
            *reinterpret_cast<float4*>(&vs[row][col]) = v4;
        }
        __syncthreads();

#pragma unroll 8
        for (int nn = 0; nn < 64; nn += 2) {
            unsigned long long kf2[4], vf2[4];
#pragma unroll
            for (int i = 0; i < 4; i++)
                kf2[i] = *reinterpret_cast<const unsigned long long*>(&ks[td + 16 * i][nn]);
#pragma unroll
            for (int j = 0; j < 4; j++)
                vf2[j] = *reinterpret_cast<const unsigned long long*>(&vs[te + 16 * j][nn]);
#pragma unroll
            for (int i = 0; i < 4; i++)
#pragma unroll
                for (int j = 0; j < 4; j++)
                    acc2[i][j] = ffma2(kf2[i], vf2[j], acc2[i][j]);
        }
        if (tid < 64) {
#pragma unroll 8
            for (int nn = 0; nn < 64; nn += 2)
                ksum2 = add2(ksum2,
                    *reinterpret_cast<const unsigned long long*>(&ks[tid][nn]));
        }
    }

    float* kvout = g_kv + (size_t)bh * DHEAD * DHEAD;
#pragma unroll
    for (int i = 0; i < 4; i++)
#pragma unroll
        for (int j = 0; j < 4; j++) {
            float lo, hi;
            unpack2(acc2[i][j], lo, hi);
            atomicAdd(&kvout[(td + 16 * i) * DHEAD + te + 16 * j], lo + hi);
        }
    if (tid < 64) {
        float lo, hi;
        unpack2(ksum2, lo, hi);
        atomicAdd(&g_ksum[bh * DHEAD + tid], lo + hi);
    }
}

// ============================================================================
// Kernel 3: out2[e,n] = (sum_d kv[d,e]*q[d,n]) * z[n], z = 1/(q . ksum + 1e-6)
// f32x2 over (n,n+1); kv duplicated per-element in smem for vector broadcast.
// Writes tf32-rounded values (out GEMM consumes them raw via cp.async).
// ============================================================================
__global__ __launch_bounds__(256) void attn_out_kernel()
{
    __shared__ float qs[64][68];
    __shared__ float kvd[64][136];   // kvd[d][2e] = kvd[d][2e+1] = kv[d][e]
    __shared__ float ksd[128];       // duplicated ksum

    const int bh = blockIdx.y;
    const int n0 = blockIdx.x * 64;
    const int tid = threadIdx.x;
    const int tn = tid & 15, te = tid >> 4;

    const float* qbase = g_q + (size_t)bh * DHEAD * NPIX;
    const float* kvbase = g_kv + (size_t)bh * DHEAD * DHEAD;

    for (int f = tid; f < 1024; f += 256) {
        const int row = f >> 4, col = (f & 15) * 4;
        float4 q4 = *reinterpret_cast<const float4*>(&qbase[(size_t)row * NPIX + n0 + col]);
        *reinterpret_cast<float4*>(&qs[row][col]) = q4;
        float4 k4 = *reinterpret_cast<const float4*>(&kvbase[f * 4]);
        float4 d0; d0.x = k4.x; d0.y = k4.x; d0.z = k4.y; d0.w = k4.y;
        float4 d1; d1.x = k4.z; d1.y = k4.z; d1.z = k4.w; d1.w = k4.w;
        *reinterpret_cast<float4*>(&kvd[row][2 * col]) = d0;
        *reinterpret_cast<float4*>(&kvd[row][2 * col + 4]) = d1;
    }
    if (tid < 64) {
        float v = g_ksum[bh * DHEAD + tid];
        ksd[2 * tid] = v; ksd[2 * tid + 1] = v;
    }
    __syncthreads();

    unsigned long long acc2[4][2];
#pragma unroll
    for (int i = 0; i < 4; ++i) { acc2[i][0] = 0ULL; acc2[i][1] = 0ULL; }
    unsigned long long den2[2] = {0ULL, 0ULL};

#pragma unroll 4
    for (int d = 0; d < 64; d++) {
        unsigned long long q2[2];
#pragma unroll
        for (int j2 = 0; j2 < 2; ++j2)
            q2[j2] = *reinterpret_cast<const unsigned long long*>(&qs[d][tn * 4 + 2 * j2]);
        unsigned long long ks2 =
            *reinterpret_cast<const unsigned long long*>(&ksd[2 * d]);
#pragma unroll
        for (int i = 0; i < 4; i++) {
            unsigned long long kf2 =
                *reinterpret_cast<const unsigned long long*>(&kvd[d][2 * (te + 16 * i)]);
#pragma unroll
            for (int j2 = 0; j2 < 2; ++j2)
                acc2[i][j2] = ffma2(kf2, q2[j2], acc2[i][j2]);
        }
#pragma unroll
        for (int j2 = 0; j2 < 2; ++j2)
            den2[j2] = ffma2(ks2, q2[j2], den2[j2]);
    }

    float z[4];
#pragma unroll
    for (int j2 = 0; j2 < 2; ++j2) {
        float lo, hi;
        unpack2(den2[j2], lo, hi);
        z[2 * j2]     = 1.0f / (lo + 1e-6f);
        z[2 * j2 + 1] = 1.0f / (hi + 1e-6f);
    }

    float* obase = g_out2 + (size_t)bh * DHEAD * NPIX;
#pragma unroll
    for (int i = 0; i < 4; i++) {
        float v0, v1, v2, v3;
        unpack2(acc2[i][0], v0, v1);
        unpack2(acc2[i][1], v2, v3);
        uint4 w;
        w.x = f2tf32(v0 * z[0]); w.y = f2tf32(v1 * z[1]);
        w.z = f2tf32(v2 * z[2]); w.w = f2tf32(v3 * z[3]);
        *reinterpret_cast<uint4*>(
            &obase[(size_t)(te + 16 * i) * NPIX + n0 + tn * 4]) = w;
    }
}

// ============================================================================
extern "C" void kernel_launch(void* const* d_in, const int* in_sizes, int n_in,
                              void* d_out, int out_size)
{
    const float* x    = (const float*)d_in[0];
    const float* cm   = (const float*)d_in[1];
    const float* Wqkv = (const float*)d_in[2];
    const float* Wout = (const float*)d_in[3];
    const float* bout = (const float*)d_in[4];
    const float* cs   = (const float*)d_in[5];
    float* y = (float*)d_out;

    cudaFuncSetAttribute(qkv_mma_kernel,
                         cudaFuncAttributeMaxDynamicSharedMemorySize, SMEM_BYTES);
    cudaFuncSetAttribute(out_mma_kernel,
                         cudaFuncAttributeMaxDynamicSharedMemorySize, SMEM_BYTES);

    void *kvp = nullptr, *ksp = nullptr;
    cudaGetSymbolAddress(&kvp, g_kv);
    cudaGetSymbolAddress(&ksp, g_ksum);
    cudaMemsetAsync(kvp, 0, sizeof(float) * BATCH * NHEAD * DHEAD * DHEAD);
    cudaMemsetAsync(ksp, 0, sizeof(float) * BATCH * NHEAD * DHEAD);

    const int pre_total = NX4 + NW14 + NW24;
    preconv_kernel<<<(pre_total + 255) / 256, 256>>>(
        (const float4*)x, (const float4*)Wqkv, (const float4*)Wout);

    qkv_mma_kernel<<<dim3(NPIX / 128, O1 / 128, BATCH), 256, SMEM_BYTES>>>(cm, cs);
    kv_ksum_kernel<<<dim3(8, BATCH * NHEAD), 256>>>();
    attn_out_kernel<<<dim3(NPIX / 64, BATCH * NHEAD), 256>>>();
    out_mma_kernel<<<dim3(NPIX / 128, CDIM / 128, BATCH), 256, SMEM_BYTES>>>(bout, y);
}

// round 5
// speedup vs baseline: 2.7788x; 1.2329x over previous
#include <cuda_runtime.h>
#include <cstdint>
#include <cstddef>

#define BATCH 8
#define CDIM  256
#define NPIX  4096
#define O1    1536
#define HIDD  512
#define NHEAD 8
#define DHEAD 64

// ---------------- scratch (device globals; no allocation allowed) ----------
__device__ float g_q[BATCH * HIDD * NPIX];      // tf32-rounded elu1(q)
__device__ float g_k[BATCH * HIDD * NPIX];      // tf32-rounded elu1(k)*(1+cs*cm)
__device__ float g_v[BATCH * HIDD * NPIX];      // tf32-rounded v
__device__ float g_out2[BATCH * HIDD * NPIX];   // tf32-rounded attention output
__device__ float g_kv[BATCH * NHEAD * DHEAD * DHEAD];
__device__ float g_ksum[BATCH * NHEAD * DHEAD];
__device__ float g_x[BATCH * CDIM * NPIX];      // tf32-rounded x
__device__ float g_wq[O1 * CDIM];               // tf32-rounded Wqkv
__device__ float g_wo[CDIM * HIDD];             // tf32-rounded Wout

// ---------------- helpers ---------------------------------------------------
__device__ __forceinline__ uint32_t f2tf32(float f) {
    uint32_t r;
    asm("cvt.rna.tf32.f32 %0, %1;" : "=r"(r) : "f"(f));
    return r;
}
__device__ __forceinline__ float elu1f(float x) {
    return x > 0.0f ? x + 1.0f : expf(x);
}
__device__ __forceinline__ void mma_tf32(float c[4], const uint32_t a[4],
                                         const uint32_t b[2]) {
    asm volatile(
        "mma.sync.aligned.m16n8k8.row.col.f32.tf32.tf32.f32 "
        "{%0,%1,%2,%3}, {%4,%5,%6,%7}, {%8,%9}, {%0,%1,%2,%3};"
        : "+f"(c[0]), "+f"(c[1]), "+f"(c[2]), "+f"(c[3])
        : "r"(a[0]), "r"(a[1]), "r"(a[2]), "r"(a[3]), "r"(b[0]), "r"(b[1]));
}
__device__ __forceinline__ void cp_async16(uint32_t dst, const void* src) {
    asm volatile("cp.async.cg.shared.global [%0], [%1], 16;" :: "r"(dst), "l"(src));
}
__device__ __forceinline__ void cp_commit() {
    asm volatile("cp.async.commit_group;");
}
template <int N> __device__ __forceinline__ void cp_wait() {
    asm volatile("cp.async.wait_group %0;" :: "n"(N));
}
__device__ __forceinline__ uint32_t smem_addr_of(const void* p) {
    uint32_t a;
    asm("{ .reg .u64 t; cvta.to.shared.u64 t, %1; cvt.u32.u64 %0, t; }"
        : "=r"(a) : "l"(p));
    return a;
}

// ===================== big-GEMM tf32 machinery (unchanged) ==================
#define A_STRIDE 36
#define B_STRIDE 136
#define A_ELEMS (128 * A_STRIDE)
#define B_ELEMS (32 * B_STRIDE)
#define BUF_ELEMS (A_ELEMS + B_ELEMS)
#define BUF_BYTES (BUF_ELEMS * 4)
#define NSTAGE 3
#define SMEM_BYTES (NSTAGE * BUF_BYTES)

struct Frag { float c[2][8][4]; };

__device__ __forceinline__ void stage_cp(
    uint32_t sbase, const float* __restrict__ A, int lda,
    const float* __restrict__ B, int ldb, int o0, int n0, int k0, int tid)
{
    const uint32_t abase = sbase;
    const uint32_t bbase = sbase + A_ELEMS * 4;
#pragma unroll
    for (int i = 0; i < 4; ++i) {
        const int fi = tid + i * 256;
        const int row = fi >> 3, c4 = (fi & 7) * 4;
        cp_async16(abase + (uint32_t)(row * A_STRIDE + c4) * 4,
                   &A[(size_t)(o0 + row) * lda + k0 + c4]);
    }
#pragma unroll
    for (int i = 0; i < 4; ++i) {
        const int fi = tid + i * 256;
        const int row = fi >> 5, c4 = (fi & 31) * 4;
        cp_async16(bbase + (uint32_t)(row * B_STRIDE + c4) * 4,
                   &B[(size_t)(k0 + row) * ldb + n0 + c4]);
    }
    cp_commit();
}

__device__ __forceinline__ void chunk_mma(
    Frag& fr, const uint32_t* sm_u, int warp_m, int warp_n, int lq, int kq)
{
    const uint32_t* As = sm_u;
    const uint32_t* Bs = sm_u + A_ELEMS;
#pragma unroll
    for (int ks = 0; ks < 4; ++ks) {
        const int kb = ks * 8 + kq;
        uint32_t a[2][4];
#pragma unroll
        for (int mt = 0; mt < 2; ++mt) {
            const int m = warp_m + mt * 16 + lq;
            a[mt][0] = As[m * A_STRIDE + kb];
            a[mt][1] = As[(m + 8) * A_STRIDE + kb];
            a[mt][2] = As[m * A_STRIDE + kb + 4];
            a[mt][3] = As[(m + 8) * A_STRIDE + kb + 4];
        }
        uint32_t bfr[8][2];
#pragma unroll
        for (int nt = 0; nt < 8; ++nt) {
            const int n = warp_n + nt * 8 + lq;
            bfr[nt][0] = Bs[kb * B_STRIDE + n];
            bfr[nt][1] = Bs[(kb + 4) * B_STRIDE + n];
        }
#pragma unroll
        for (int mt = 0; mt < 2; ++mt)
#pragma unroll
            for (int nt = 0; nt < 8; ++nt)
                mma_tf32(fr.c[mt][nt], a[mt], bfr[nt]);
    }
}

__device__ __forceinline__ void gemm_mainloop(
    Frag& fr, const float* __restrict__ A, int lda,
    const float* __restrict__ B, int ldb,
    int o0, int n0, int K, uint32_t* sm_u)
{
    const int tid = threadIdx.x;
    const int wid = tid >> 5, lane = tid & 31;
    const int warp_m = (wid & 3) * 32;
    const int warp_n = (wid >> 2) * 64;
    const int lq = lane >> 2, kq = lane & 3;
    const int NC = K / 32;

    const uint32_t sbase = smem_addr_of(sm_u);

#pragma unroll
    for (int mt = 0; mt < 2; ++mt)
#pragma unroll
        for (int nt = 0; nt < 8; ++nt)
#pragma unroll
            for (int i = 0; i < 4; ++i) fr.c[mt][nt][i] = 0.0f;

    stage_cp(sbase, A, lda, B, ldb, o0, n0, 0, tid);
    stage_cp(sbase + BUF_BYTES, A, lda, B, ldb, o0, n0, 32, tid);

    for (int c = 0; c < NC; ++c) {
        if (c < NC - 1) cp_wait<1>(); else cp_wait<0>();
        __syncthreads();
        if (c + 2 < NC)
            stage_cp(sbase + (uint32_t)((c + 2) % 3) * BUF_BYTES,
                     A, lda, B, ldb, o0, n0, (c + 2) * 32, tid);
        chunk_mma(fr, sm_u + (size_t)(c % 3) * BUF_ELEMS, warp_m, warp_n, lq, kq);
    }
}

// ============================================================================
// Kernel 0: round x, Wqkv, Wout to tf32 into scratch.
// ============================================================================
#define NX4  (BATCH * CDIM * NPIX / 4)
#define NW14 (O1 * CDIM / 4)
#define NW24 (CDIM * HIDD / 4)

__global__ __launch_bounds__(256) void preconv_kernel(
    const float4* __restrict__ x, const float4* __restrict__ wq,
    const float4* __restrict__ wo)
{
    const int i = blockIdx.x * 256 + threadIdx.x;
    float4 v;
    uint4* dst;
    if (i < NX4) {
        v = x[i]; dst = reinterpret_cast<uint4*>(g_x) + i;
    } else if (i < NX4 + NW14) {
        v = wq[i - NX4]; dst = reinterpret_cast<uint4*>(g_wq) + (i - NX4);
    } else if (i < NX4 + NW14 + NW24) {
        v = wo[i - NX4 - NW14];
        dst = reinterpret_cast<uint4*>(g_wo) + (i - NX4 - NW14);
    } else {
        return;
    }
    uint4 t;
    t.x = f2tf32(v.x); t.y = f2tf32(v.y); t.z = f2tf32(v.z); t.w = f2tf32(v.w);
    *dst = t;
}

// ============================================================================
// Kernel 1: qkv GEMM; epilogue writes tf32-rounded q/k/v.
// ============================================================================
__global__ __launch_bounds__(256, 2) void qkv_mma_kernel(
    const float* __restrict__ cm, const float* __restrict__ csp)
{
    extern __shared__ uint32_t sm_u[];
    const int b  = blockIdx.z;
    const int o0 = blockIdx.y * 128;
    const int n0 = blockIdx.x * 128;

    Frag fr;
    gemm_mainloop(fr, g_wq, CDIM, g_x + (size_t)b * CDIM * NPIX, NPIX,
                  o0, n0, CDIM, sm_u);

    const int tid = threadIdx.x;
    const int wid = tid >> 5, lane = tid & 31;
    const int warp_m = (wid & 3) * 32;
    const int warp_n = (wid >> 2) * 64;
    const int lq = lane >> 2, kq = lane & 3;

    const int sec = o0 >> 9;                 // 0=q, 1=k, 2=v
    const int obase = o0 & 511;
    float* dst = (sec == 0) ? g_q : (sec == 1) ? g_k : g_v;
    const float cs = (sec == 1) ? *csp : 0.0f;
    const float* cmb = cm + (size_t)b * NPIX;

#pragma unroll
    for (int nt = 0; nt < 8; ++nt) {
        const int cg = n0 + warp_n + nt * 8 + kq * 2;
        float m0 = 1.0f, m1 = 1.0f;
        if (sec == 1) {
            m0 = 1.0f + cs * cmb[cg];
            m1 = 1.0f + cs * cmb[cg + 1];
        }
#pragma unroll
        for (int mt = 0; mt < 2; ++mt) {
            const int rl = warp_m + mt * 16 + lq;
#pragma unroll
            for (int ri = 0; ri < 2; ++ri) {
                const int grow = obase + rl + ri * 8;
                float v0 = fr.c[mt][nt][2 * ri + 0];
                float v1 = fr.c[mt][nt][2 * ri + 1];
                if (sec == 0)      { v0 = elu1f(v0);       v1 = elu1f(v1); }
                else if (sec == 1) { v0 = elu1f(v0) * m0;  v1 = elu1f(v1) * m1; }
                uint2 w;
                w.x = f2tf32(v0); w.y = f2tf32(v1);
                *reinterpret_cast<uint2*>(
                    &dst[((size_t)b * HIDD + grow) * NPIX + cg]) = w;
            }
        }
    }
}

// ============================================================================
// Kernel 4: y = Wout @ out2 + bout
// ============================================================================
__global__ __launch_bounds__(256, 2) void out_mma_kernel(
    const float* __restrict__ bout, float* __restrict__ y)
{
    extern __shared__ uint32_t sm_u[];
    const int b  = blockIdx.z;
    const int o0 = blockIdx.y * 128;
    const int n0 = blockIdx.x * 128;

    Frag fr;
    gemm_mainloop(fr, g_wo, HIDD, g_out2 + (size_t)b * HIDD * NPIX, NPIX,
                  o0, n0, HIDD, sm_u);

    const int tid = threadIdx.x;
    const int wid = tid >> 5, lane = tid & 31;
    const int warp_m = (wid & 3) * 32;
    const int warp_n = (wid >> 2) * 64;
    const int lq = lane >> 2, kq = lane & 3;

#pragma unroll
    for (int mt = 0; mt < 2; ++mt) {
        const int rl = warp_m + mt * 16 + lq;
#pragma unroll
        for (int ri = 0; ri < 2; ++ri) {
            const int grow = o0 + rl + ri * 8;
            const float bo = bout[grow];
#pragma unroll
            for (int nt = 0; nt < 8; ++nt) {
                const int cg = n0 + warp_n + nt * 8 + kq * 2;
                float2 w;
                w.x = fr.c[mt][nt][2 * ri + 0] + bo;
                w.y = fr.c[mt][nt][2 * ri + 1] + bo;
                *reinterpret_cast<float2*>(
                    &y[((size_t)b * CDIM + grow) * NPIX + cg]) = w;
            }
        }
    }
}

// ============================================================================
// Kernel 2 (MMA): per (bh): A=k[d][n] (cp.async), B=v^T[n][e] + ones col e=64.
// out[d][e<64] -> kv (atomic), out[d][64] -> ksum (atomic). N=80, M=64.
// Grid (4 n-splits, 64 bh). K per CTA = 1024 in 16 chunks of 64, dbl-buffered.
// ============================================================================
#define KV_ASTR 68
#define KV_BSTR 88
#define KV_AE (64 * KV_ASTR)      // 4352 floats
#define KV_BE (64 * KV_BSTR)      // 5632 floats
#define KV_SMEM_BYTES ((2 * KV_AE + 2 * KV_BE) * 4)   // 79872

__global__ __launch_bounds__(256) void kv_mma_kernel()
{
    extern __shared__ uint32_t sm_u[];
    uint32_t* As = sm_u;                       // 2 x [64][KV_ASTR]
    uint32_t* Bs = sm_u + 2 * KV_AE;           // 2 x [64][KV_BSTR]
    const uint32_t a_sbase = smem_addr_of(As);

    const int bh    = blockIdx.y;
    const int split = blockIdx.x;
    const int tid = threadIdx.x;
    const int wid = tid >> 5, lane = tid & 31;
    const int warp_m = (wid & 3) * 16;
    const int warp_n = (wid >> 2) * 40;
    const int lq = lane >> 2, kq = lane & 3;

    const float* kbase = g_k + (size_t)bh * DHEAD * NPIX + split * 1024;
    const float* vbase = g_v + (size_t)bh * DHEAD * NPIX + split * 1024;

    // ones column (e=64) and zero cols 65..79, both buffers; never rewritten.
    for (int f = tid; f < 64 * 16 * 2; f += 256) {
        const int buf = f >> 10;
        const int r = (f >> 4) & 63, cc = 64 + (f & 15);
        Bs[buf * KV_BE + r * KV_BSTR + cc] =
            (cc == 64) ? 0x3f800000u : 0u;   // tf32(1.0) == fp32 1.0 bits
    }

    float fr[5][4];
#pragma unroll
    for (int nt = 0; nt < 5; ++nt)
#pragma unroll
        for (int i = 0; i < 4; ++i) fr[nt][i] = 0.0f;

    // v prefetch regs: 4 x float4; thread -> (e = f&63, n4 = (f>>6)*4)
    float4 vreg[4];
    auto load_v = [&](int n0) {
#pragma unroll
        for (int i = 0; i < 4; ++i) {
            const int f = tid + i * 256;
            const int e = f & 63, n4 = (f >> 6) * 4;
            vreg[i] = *reinterpret_cast<const float4*>(
                &vbase[(size_t)e * NPIX + n0 + n4]);
        }
    };
    auto store_v = [&](int buf) {
#pragma unroll
        for (int i = 0; i < 4; ++i) {
            const int f = tid + i * 256;
            const int e = f & 63, n4 = (f >> 6) * 4;
            uint32_t* bb = Bs + buf * KV_BE;
            bb[(n4 + 0) * KV_BSTR + e] = f2tf32(vreg[i].x);
            bb[(n4 + 1) * KV_BSTR + e] = f2tf32(vreg[i].y);
            bb[(n4 + 2) * KV_BSTR + e] = f2tf32(vreg[i].z);
            bb[(n4 + 3) * KV_BSTR + e] = f2tf32(vreg[i].w);
        }
    };
    auto stage_k = [&](int n0, int buf) {
#pragma unroll
        for (int i = 0; i < 4; ++i) {
            const int f = tid + i * 256;
            const int d = f >> 4, c4 = (f & 15) * 4;
            cp_async16(a_sbase + (uint32_t)(buf * KV_AE + d * KV_ASTR + c4) * 4,
                       &kbase[(size_t)d * NPIX + n0 + c4]);
        }
        cp_commit();
    };

    load_v(0);
    stage_k(0, 0);
    store_v(0);
    cp_wait<0>();
    __syncthreads();

    for (int c = 0; c < 16; ++c) {
        const int cur = c & 1;
        if (c < 15) {
            load_v((c + 1) * 64);
            stage_k((c + 1) * 64, cur ^ 1);
        }
        // MMA over chunk c
        const uint32_t* Ab = As + cur * KV_AE;
        const uint32_t* Bb = Bs + cur * KV_BE;
#pragma unroll
        for (int ks = 0; ks < 8; ++ks) {
            const int kb = ks * 8 + kq;
            uint32_t a[4];
            a[0] = Ab[(warp_m + lq) * KV_ASTR + kb];
            a[1] = Ab[(warp_m + lq + 8) * KV_ASTR + kb];
            a[2] = Ab[(warp_m + lq) * KV_ASTR + kb + 4];
            a[3] = Ab[(warp_m + lq + 8) * KV_ASTR + kb + 4];
            uint32_t bfr[5][2];
#pragma unroll
            for (int nt = 0; nt < 5; ++nt) {
                const int n = warp_n + nt * 8 + lq;
                bfr[nt][0] = Bb[kb * KV_BSTR + n];
                bfr[nt][1] = Bb[(kb + 4) * KV_BSTR + n];
            }
#pragma unroll
            for (int nt = 0; nt < 5; ++nt)
                mma_tf32(fr[nt], a, bfr[nt]);
        }
        if (c < 15) {
            store_v(cur ^ 1);
            cp_wait<0>();
            __syncthreads();
        }
    }

    float* kvout = g_kv + (size_t)bh * DHEAD * DHEAD;
    float* ksout = g_ksum + (size_t)bh * DHEAD;
#pragma unroll
    for (int nt = 0; nt < 5; ++nt) {
#pragma unroll
        for (int i = 0; i < 4; ++i) {
            const int e = warp_n + nt * 8 + kq * 2 + (i & 1);
            const int d = warp_m + lq + (i >> 1) * 8;
            if (e < 64)       atomicAdd(&kvout[d * DHEAD + e], fr[nt][i]);
            else if (e == 64) atomicAdd(&ksout[d], fr[nt][i]);
        }
    }
}

// ============================================================================
// Kernel 3 (MMA): A = [kv^T (rows 0..63); ksum (row 64); 0 (rows 65..79)],
// B = q[d][n] tile (cp.async). Row 64 of D = q.ksum -> z via shfl.
// out2[e][n] = D[e][n] * z[n], tf32-rounded. Grid (32 n-tiles of 128, 64 bh).
// ============================================================================
#define AT_ASTR 68
#define AT_BSTR 136
#define AT_AE (80 * AT_ASTR)      // 5440 floats
#define AT_BE (64 * AT_BSTR)      // 8704 floats
#define AT_SMEM_BYTES ((AT_AE + AT_BE) * 4)   // 56576

__global__ __launch_bounds__(256) void attn_mma_kernel()
{
    extern __shared__ uint32_t sm_u[];
    uint32_t* As = sm_u;
    uint32_t* Bs = sm_u + AT_AE;
    const uint32_t b_sbase = smem_addr_of(Bs);

    const int bh = blockIdx.y;
    const int n0 = blockIdx.x * 128;
    const int tid = threadIdx.x;
    const int wid = tid >> 5, lane = tid & 31;
    const int warp_n = wid * 16;
    const int lq = lane >> 2, kq = lane & 3;

    const float* qbase  = g_q  + (size_t)bh * DHEAD * NPIX;
    const float* kvbase = g_kv + (size_t)bh * DHEAD * DHEAD;

    // B: q tile [64 d][128 n] via cp.async
#pragma unroll
    for (int i = 0; i < 8; ++i) {
        const int f = tid + i * 256;
        const int d = f >> 5, c4 = (f & 31) * 4;
        cp_async16(b_sbase + (uint32_t)(d * AT_BSTR + c4) * 4,
                   &qbase[(size_t)d * NPIX + n0 + c4]);
    }
    cp_commit();

    // A rows 65..79 zero
    for (int f = tid; f < 15 * AT_ASTR; f += 256) As[65 * AT_ASTR + f] = 0u;
    // A row 64 = ksum
    if (tid < 64) As[64 * AT_ASTR + tid] = f2tf32(g_ksum[bh * DHEAD + tid]);
    // A rows 0..63 = kv^T
#pragma unroll
    for (int i = 0; i < 4; ++i) {
        const int f = tid + i * 256;
        const int d = f & 63, e4 = (f >> 6) * 4;
        float4 v = *reinterpret_cast<const float4*>(&kvbase[d * DHEAD + e4]);
        As[(e4 + 0) * AT_ASTR + d] = f2tf32(v.x);
        As[(e4 + 1) * AT_ASTR + d] = f2tf32(v.y);
        As[(e4 + 2) * AT_ASTR + d] = f2tf32(v.z);
        As[(e4 + 3) * AT_ASTR + d] = f2tf32(v.w);
    }
    cp_wait<0>();
    __syncthreads();

    float fr[5][2][4];
#pragma unroll
    for (int mt = 0; mt < 5; ++mt)
#pragma unroll
        for (int nt = 0; nt < 2; ++nt)
#pragma unroll
            for (int i = 0; i < 4; ++i) fr[mt][nt][i] = 0.0f;

#pragma unroll
    for (int ks = 0; ks < 8; ++ks) {
        const int kb = ks * 8 + kq;
        uint32_t a[5][4];
#pragma unroll
        for (int mt = 0; mt < 5; ++mt) {
            const int m = mt * 16 + lq;
            a[mt][0] = As[m * AT_ASTR + kb];
            a[mt][1] = As[(m + 8) * AT_ASTR + kb];
            a[mt][2] = As[m * AT_ASTR + kb + 4];
            a[mt][3] = As[(m + 8) * AT_ASTR + kb + 4];
        }
        uint32_t bfr[2][2];
#pragma unroll
        for (int nt = 0; nt < 2; ++nt) {
            const int n = warp_n + nt * 8 + lq;
            bfr[nt][0] = Bs[kb * AT_BSTR + n];
            bfr[nt][1] = Bs[(kb + 4) * AT_BSTR + n];
        }
#pragma unroll
        for (int mt = 0; mt < 5; ++mt)
#pragma unroll
            for (int nt = 0; nt < 2; ++nt)
                mma_tf32(fr[mt][nt], a[mt], bfr[nt]);
    }

    // Epilogue: z from row 64 (m-tile 4, local row 0 -> lanes lq==0, lane==kq)
    float* obase = g_out2 + (size_t)bh * DHEAD * NPIX;
#pragma unroll
    for (int nt = 0; nt < 2; ++nt) {
        const float den0 = __shfl_sync(0xffffffffu, fr[4][nt][0], kq);
        const float den1 = __shfl_sync(0xffffffffu, fr[4][nt][1], kq);
        const float z0 = 1.0f / (den0 + 1e-6f);
        const float z1 = 1.0f / (den1 + 1e-6f);
        const int cg = n0 + warp_n + nt * 8 + kq * 2;
#pragma unroll
        for (int mt = 0; mt < 4; ++mt) {
            const int r0 = mt * 16 + lq;
            uint2 w;
            w.x = f2tf32(fr[mt][nt][0] * z0);
            w.y = f2tf32(fr[mt][nt][1] * z1);
            *reinterpret_cast<uint2*>(&obase[(size_t)r0 * NPIX + cg]) = w;
            w.x = f2tf32(fr[mt][nt][2] * z0);
            w.y = f2tf32(fr[mt][nt][3] * z1);
            *reinterpret_cast<uint2*>(&obase[(size_t)(r0 + 8) * NPIX + cg]) = w;
        }
    }
}

// ============================================================================
extern "C" void kernel_launch(void* const* d_in, const int* in_sizes, int n_in,
                              void* d_out, int out_size)
{
    const float* x    = (const float*)d_in[0];
    const float* cm   = (const float*)d_in[1];
    const float* Wqkv = (const float*)d_in[2];
    const float* Wout = (const float*)d_in[3];
    const float* bout = (const float*)d_in[4];
    const float* cs   = (const float*)d_in[5];
    float* y = (float*)d_out;

    cudaFuncSetAttribute(qkv_mma_kernel,
                         cudaFuncAttributeMaxDynamicSharedMemorySize, SMEM_BYTES);
    cudaFuncSetAttribute(out_mma_kernel,
                         cudaFuncAttributeMaxDynamicSharedMemorySize, SMEM_BYTES);
    cudaFuncSetAttribute(kv_mma_kernel,
                         cudaFuncAttributeMaxDynamicSharedMemorySize, KV_SMEM_BYTES);
    cudaFuncSetAttribute(attn_mma_kernel,
                         cudaFuncAttributeMaxDynamicSharedMemorySize, AT_SMEM_BYTES);

    void *kvp = nullptr, *ksp = nullptr;
    cudaGetSymbolAddress(&kvp, g_kv);
    cudaGetSymbolAddress(&ksp, g_ksum);
    cudaMemsetAsync(kvp, 0, sizeof(float) * BATCH * NHEAD * DHEAD * DHEAD);
    cudaMemsetAsync(ksp, 0, sizeof(float) * BATCH * NHEAD * DHEAD);

    const int pre_total = NX4 + NW14 + NW24;
    preconv_kernel<<<(pre_total + 255) / 256, 256>>>(
        (const float4*)x, (const float4*)Wqkv, (const float4*)Wout);

    qkv_mma_kernel<<<dim3(NPIX / 128, O1 / 128, BATCH), 256, SMEM_BYTES>>>(cm, cs);
    kv_mma_kernel<<<dim3(4, BATCH * NHEAD), 256, KV_SMEM_BYTES>>>();
    attn_mma_kernel<<<dim3(NPIX / 128, BATCH * NHEAD), 256, AT_SMEM_BYTES>>>();
    out_mma_kernel<<<dim3(NPIX / 128, CDIM / 128, BATCH), 256, SMEM_BYTES>>>(bout, y);
}